// round 7
// baseline (speedup 1.0000x reference)
#include <cuda_runtime.h>
#include <cstdint>

// SDDMM: out[i] = mask_vals[i] + dot(mat1[rows[i], :], mat2[:, cols[i]])
// Inputs: mask_vals f32[1e6], rows i32[1e6], cols i32[1e6],
//         mat1 f32[8192,128], mat2 f32[128,8192]   Output: f32[1e6]

#define NNZ  1000000
#define MDIM 8192
#define NDIM 8192
#define KDIM 128

#define RBBITS 8                        // 256 rows per rowblock
#define NBUCK  ((MDIM >> RBBITS) * NDIM)  // 262144 buckets: (row>>8)*8192 + col

#define SDDMM_BLOCKS 148                // one per SM -> private 128KB row slab
#define CHUNK 6760                      // ceil(NNZ/148) rounded to mult of 4

typedef unsigned long long u64;

// Static scratch (no allocations anywhere)
__device__ float g_mat2T[(size_t)NDIM * KDIM];
__device__ int   g_buck[NBUCK];
__device__ int   g_cursor[NBUCK];
__device__ int   g_part[256];
__device__ u64   g_rcp[NNZ];            // (row<<33)|(col<<20)|orig_index

// ---------------------------------------------------------------------------
// Transpose mat2 [K, N] -> g_mat2T [N, K]
// ---------------------------------------------------------------------------
__global__ void transpose_k(const float* __restrict__ mat2) {
    __shared__ float tile[32][33];
    const int n0 = blockIdx.x * 32;
    const int k0 = blockIdx.y * 32;
    #pragma unroll
    for (int r = threadIdx.y; r < 32; r += 8)
        tile[r][threadIdx.x] = mat2[(size_t)(k0 + r) * NDIM + n0 + threadIdx.x];
    __syncthreads();
    #pragma unroll
    for (int r = threadIdx.y; r < 32; r += 8)
        g_mat2T[(size_t)(n0 + r) * KDIM + k0 + threadIdx.x] = tile[threadIdx.x][r];
}

// ---------------------------------------------------------------------------
// Counting sort by key = (row>>8)*8192 + col
// ---------------------------------------------------------------------------
__device__ __forceinline__ int make_key(int r, int c) {
    return ((r >> RBBITS) << 13) | c;
}

__global__ void zero_k() {   // grid 64 x 1024, int4 stores
    int4 z = make_int4(0, 0, 0, 0);
    reinterpret_cast<int4*>(g_buck)[blockIdx.x * blockDim.x + threadIdx.x] = z;
}

__global__ void hist_k(const int* __restrict__ rows,
                       const int* __restrict__ cols) {
    const int base = (blockIdx.x * blockDim.x + threadIdx.x) * 4;
    if (base >= NNZ) return;
    const int4 r = *reinterpret_cast<const int4*>(rows + base);
    const int4 c = *reinterpret_cast<const int4*>(cols + base);
    atomicAdd(&g_buck[make_key(r.x, c.x)], 1);
    atomicAdd(&g_buck[make_key(r.y, c.y)], 1);
    atomicAdd(&g_buck[make_key(r.z, c.z)], 1);
    atomicAdd(&g_buck[make_key(r.w, c.w)], 1);
}

// Pass 1: block b sums g_buck[b*1024 .. b*1024+1024) -> g_part[b]. grid 256x256.
__global__ void scan1_k() {
    __shared__ int sh[8];
    const int t = threadIdx.x;
    const int4 v = reinterpret_cast<const int4*>(g_buck + blockIdx.x * 1024)[t];
    int s = v.x + v.y + v.z + v.w;
    #pragma unroll
    for (int o = 16; o > 0; o >>= 1) s += __shfl_xor_sync(~0u, s, o);
    if ((t & 31) == 0) sh[t >> 5] = s;
    __syncthreads();
    if (t == 0) {
        int tot = 0;
        #pragma unroll
        for (int k = 0; k < 8; k++) tot += sh[k];
        g_part[blockIdx.x] = tot;
    }
}

// Pass 2: exclusive scan of 256 partials. 1 block x 256, warp-shuffle based.
__global__ void scan2_k() {
    __shared__ int wsum[8];
    const int t = threadIdx.x;
    const int v = g_part[t];
    int x = v;
    #pragma unroll
    for (int o = 1; o < 32; o <<= 1) {
        int y = __shfl_up_sync(~0u, x, o);
        if ((t & 31) >= o) x += y;
    }
    if ((t & 31) == 31) wsum[t >> 5] = x;
    __syncthreads();
    if (t < 8) {
        int s = wsum[t];
        #pragma unroll
        for (int o = 1; o < 8; o <<= 1) {
            int y = __shfl_up_sync(0xFFu, s, o);
            if (t >= o) s += y;
        }
        wsum[t] = s;
    }
    __syncthreads();
    const int base = (t >= 32) ? wsum[(t >> 5) - 1] : 0;
    g_part[t] = base + x - v;      // exclusive
}

// Pass 3: per-element exclusive scan + block offset -> g_cursor. grid 256x256.
__global__ void scan3_k() {
    __shared__ int wsum[8];
    const int t = threadIdx.x;
    const int b = blockIdx.x;
    const int4 v = reinterpret_cast<const int4*>(g_buck + b * 1024)[t];
    const int s0 = v.x, s1 = v.x + v.y, s2 = s1 + v.z, s3 = s2 + v.w;
    int x = s3;
    #pragma unroll
    for (int o = 1; o < 32; o <<= 1) {
        int y = __shfl_up_sync(~0u, x, o);
        if ((t & 31) >= o) x += y;
    }
    if ((t & 31) == 31) wsum[t >> 5] = x;
    __syncthreads();
    if (t < 8) {
        int s = wsum[t];
        #pragma unroll
        for (int o = 1; o < 8; o <<= 1) {
            int y = __shfl_up_sync(0xFFu, s, o);
            if (t >= o) s += y;
        }
        wsum[t] = s;
    }
    __syncthreads();
    const int base = g_part[b] + ((t >= 32) ? wsum[(t >> 5) - 1] : 0) + (x - s3);
    int4 cur;
    cur.x = base; cur.y = base + s0; cur.z = base + s1; cur.w = base + s2;
    reinterpret_cast<int4*>(g_cursor + b * 1024)[t] = cur;
}

__global__ void scatter_k(const int* __restrict__ rows,
                          const int* __restrict__ cols) {
    const int base = (blockIdx.x * blockDim.x + threadIdx.x) * 4;
    if (base >= NNZ) return;
    const int4 r = *reinterpret_cast<const int4*>(rows + base);
    const int4 c = *reinterpret_cast<const int4*>(cols + base);
    #pragma unroll
    for (int j = 0; j < 4; j++) {
        const int rr = (j == 0) ? r.x : (j == 1) ? r.y : (j == 2) ? r.z : r.w;
        const int cc = (j == 0) ? c.x : (j == 1) ? c.y : (j == 2) ? c.z : c.w;
        const int p  = atomicAdd(&g_cursor[make_key(rr, cc)], 1);
        g_rcp[p] = ((u64)rr << 33) | ((u64)cc << 20) | (u64)(base + j);
    }
}

// ---------------------------------------------------------------------------
// SDDMM over (rowblock, col)-sorted nnz. One block per SM, 512 threads.
// Each block owns one contiguous chunk: rows confined to one 256-row slab
// (128KB, L1-resident); columns streamed with __ldcs (evict-first) so they
// don't evict the row slab. Equal-col runs are adjacent -> L1 dedup.
// 8 lanes per nnz, 4 nnz per warp-iteration, 16 warps interleaved.
// ---------------------------------------------------------------------------
__global__ void __launch_bounds__(512)
sddmm_k(const float* __restrict__ mask_vals,
        const float* __restrict__ mat1,
        float* __restrict__ out) {
    const int lane = threadIdx.x & 31;
    const int sub  = lane & 7;
    const int grp  = lane >> 3;
    const int w    = threadIdx.x >> 5;          // warp in block (0..15)

    const int start = blockIdx.x * CHUNK;
    const int end   = min(start + CHUNK, NNZ);

    for (int base = start + w * 4; base < end; base += 16 * 4) {
        const int j     = base + grp;
        const bool live = (j < end);
        const u64 rcp   = live ? g_rcp[j] : 0ull;
        const int r = (int)(rcp >> 33);
        const int c = (int)(rcp >> 20) & 0x1FFF;
        const int i = (int)(rcp & 0xFFFFF);

        const float4* __restrict__ a4 =
            reinterpret_cast<const float4*>(mat1 + (size_t)r * KDIM);
        const float4* __restrict__ b4 =
            reinterpret_cast<const float4*>(g_mat2T + (size_t)c * KDIM);

        const float4 a0 = a4[sub];
        const float4 b0 = __ldcs(b4 + sub);
        const float4 a1 = a4[sub + 8];
        const float4 b1 = __ldcs(b4 + sub + 8);
        const float4 a2 = a4[sub + 16];
        const float4 b2 = __ldcs(b4 + sub + 16);
        const float4 a3 = a4[sub + 24];
        const float4 b3 = __ldcs(b4 + sub + 24);

        float s = a0.x * b0.x;
        s = fmaf(a0.y, b0.y, s); s = fmaf(a0.z, b0.z, s); s = fmaf(a0.w, b0.w, s);
        s = fmaf(a1.x, b1.x, s); s = fmaf(a1.y, b1.y, s);
        s = fmaf(a1.z, b1.z, s); s = fmaf(a1.w, b1.w, s);
        s = fmaf(a2.x, b2.x, s); s = fmaf(a2.y, b2.y, s);
        s = fmaf(a2.z, b2.z, s); s = fmaf(a2.w, b2.w, s);
        s = fmaf(a3.x, b3.x, s); s = fmaf(a3.y, b3.y, s);
        s = fmaf(a3.z, b3.z, s); s = fmaf(a3.w, b3.w, s);

        s += __shfl_xor_sync(0xFFFFFFFFu, s, 4);
        s += __shfl_xor_sync(0xFFFFFFFFu, s, 2);
        s += __shfl_xor_sync(0xFFFFFFFFu, s, 1);

        if (sub == 0 && live)
            out[i] = __ldcs(mask_vals + i) + s;
    }
}

extern "C" void kernel_launch(void* const* d_in, const int* in_sizes, int n_in,
                              void* d_out, int out_size) {
    const float* mask_vals = (const float*)d_in[0];
    const int*   rows      = (const int*)d_in[1];
    const int*   cols      = (const int*)d_in[2];
    const float* mat1      = (const float*)d_in[3];
    const float* mat2      = (const float*)d_in[4];
    float*       out       = (float*)d_out;

    transpose_k<<<dim3(NDIM / 32, KDIM / 32), dim3(32, 8)>>>(mat2);

    zero_k<<<NBUCK / 4 / 1024, 1024>>>();
    hist_k<<<(NNZ / 4 + 255) / 256, 256>>>(rows, cols);
    scan1_k<<<256, 256>>>();
    scan2_k<<<1, 256>>>();
    scan3_k<<<256, 256>>>();
    scatter_k<<<(NNZ / 4 + 255) / 256, 256>>>(rows, cols);

    sddmm_k<<<SDDMM_BLOCKS, 512>>>(mask_vals, mat1, out);
}

// round 8
// speedup vs baseline: 2.7954x; 2.7954x over previous
#include <cuda_runtime.h>
#include <cuda_fp16.h>
#include <cstdint>

// SDDMM: out[i] = mask_vals[i] + dot(mat1[rows[i], :], mat2[:, cols[i]])
// Inputs: mask_vals f32[1e6], rows i32[1e6], cols i32[1e6],
//         mat1 f32[8192,128], mat2 f32[128,8192]   Output: f32[1e6]
//
// Strategy: the gather streams are L2-throughput-bound. Halve the bytes by
// staging both matrices as fp16 (2MB each), accumulate in fp32.

#define NNZ  1000000
#define MDIM 8192
#define NDIM 8192
#define KDIM 128

// Static scratch (no allocations anywhere)
__device__ __half g_m1h[(size_t)MDIM * KDIM];   // mat1 as fp16 [M, K]
__device__ __half g_m2Th[(size_t)NDIM * KDIM];  // mat2^T as fp16 [N, K]

// ---------------------------------------------------------------------------
// Convert mat1 [M, K] f32 -> g_m1h fp16 (coalesced, 4 elems/thread)
// ---------------------------------------------------------------------------
__global__ void conv1_k(const float* __restrict__ mat1) {
    const int t = blockIdx.x * blockDim.x + threadIdx.x;   // 262144 threads
    const float4 v = reinterpret_cast<const float4*>(mat1)[t];
    __half2 h0 = __floats2half2_rn(v.x, v.y);
    __half2 h1 = __floats2half2_rn(v.z, v.w);
    uint2 pack;
    pack.x = *reinterpret_cast<unsigned int*>(&h0);
    pack.y = *reinterpret_cast<unsigned int*>(&h1);
    reinterpret_cast<uint2*>(g_m1h)[t] = pack;
}

// ---------------------------------------------------------------------------
// Transpose-convert mat2 [K, N] f32 -> g_m2Th fp16 [N, K]
// ---------------------------------------------------------------------------
__global__ void conv2_k(const float* __restrict__ mat2) {
    __shared__ float tile[32][33];
    const int n0 = blockIdx.x * 32;
    const int k0 = blockIdx.y * 32;
    #pragma unroll
    for (int r = threadIdx.y; r < 32; r += 8)
        tile[r][threadIdx.x] = mat2[(size_t)(k0 + r) * NDIM + n0 + threadIdx.x];
    __syncthreads();
    #pragma unroll
    for (int r = threadIdx.y; r < 32; r += 8)
        g_m2Th[(size_t)(n0 + r) * KDIM + k0 + threadIdx.x] =
            __float2half_rn(tile[threadIdx.x][r]);
}

// ---------------------------------------------------------------------------
// 8 halves (one float4 worth) dotted into an fp32 accumulator
// ---------------------------------------------------------------------------
__device__ __forceinline__ float dot8(float4 av, float4 bv, float s) {
    const __half2* ah = reinterpret_cast<const __half2*>(&av);
    const __half2* bh = reinterpret_cast<const __half2*>(&bv);
    #pragma unroll
    for (int k = 0; k < 4; k++) {
        const float2 fa = __half22float2(ah[k]);
        const float2 fb = __half22float2(bh[k]);
        s = fmaf(fa.x, fb.x, s);
        s = fmaf(fa.y, fb.y, s);
    }
    return s;
}

// ---------------------------------------------------------------------------
// Grid-stride SDDMM: 8 lanes per nnz, 4 nnz per warp-iteration.
// Row/col are fp16: one row = 256B = 16 float4-chunks; lane sub covers
// chunks {sub, sub+8} of each matrix -> 4 LDG.128 per lane-iter (MLP=4),
// 16 wavefronts per warp-iter (4 wf/nnz, half of the fp32 version).
// fp32 accumulate -> 3-step 8-lane butterfly -> lane 0 stores.
// ---------------------------------------------------------------------------
__global__ void __launch_bounds__(256)
sddmm_k(const float* __restrict__ mask_vals,
        const int* __restrict__ rows,
        const int* __restrict__ cols,
        float* __restrict__ out) {
    const int lane   = threadIdx.x & 31;
    const int sub    = lane & 7;
    const int grp    = lane >> 3;
    const int gwarp  = (blockIdx.x * blockDim.x + threadIdx.x) >> 5;
    const int nwarps = (gridDim.x * blockDim.x) >> 5;

    for (int base = gwarp * 4; base < NNZ; base += nwarps * 4) {
        const int i = base + grp;
        const int r = rows[i];          // one sector per warp (4 adjacent i)
        const int c = cols[i];

        const float4* __restrict__ a4 =
            reinterpret_cast<const float4*>(g_m1h + (size_t)r * KDIM);
        const float4* __restrict__ b4 =
            reinterpret_cast<const float4*>(g_m2Th + (size_t)c * KDIM);

        // 4 independent LDG.128 (each covers 8 fp16 values)
        const float4 aL = a4[sub];
        const float4 bL = b4[sub];
        const float4 aH = a4[sub + 8];
        const float4 bH = b4[sub + 8];

        float s = dot8(aL, bL, 0.0f);
        s = dot8(aH, bH, s);

        // Reduce within the 8-lane group
        s += __shfl_xor_sync(0xFFFFFFFFu, s, 4);
        s += __shfl_xor_sync(0xFFFFFFFFu, s, 2);
        s += __shfl_xor_sync(0xFFFFFFFFu, s, 1);

        if (sub == 0)                   // lanes 0,8,16,24
            out[i] = mask_vals[i] + s;
    }
}

extern "C" void kernel_launch(void* const* d_in, const int* in_sizes, int n_in,
                              void* d_out, int out_size) {
    const float* mask_vals = (const float*)d_in[0];
    const int*   rows      = (const int*)d_in[1];
    const int*   cols      = (const int*)d_in[2];
    const float* mat1      = (const float*)d_in[3];
    const float* mat2      = (const float*)d_in[4];
    float*       out       = (float*)d_out;

    // Stage matrices as fp16
    conv1_k<<<(MDIM * KDIM / 4) / 256, 256>>>(mat1);
    conv2_k<<<dim3(NDIM / 32, KDIM / 32), dim3(32, 8)>>>(mat2);

    // SDDMM
    const int blocks = 148 * 8;
    sddmm_k<<<blocks, 256>>>(mask_vals, rows, cols, out);
}